// round 9
// baseline (speedup 1.0000x reference)
#include <cuda_runtime.h>
#include <cuda.h>

// BilinearResNet fused, GB300 sm_103a — round 9
// Round-7 proven pipeline (TMA double-buffer + per-chunk syncthreads),
// W via __ldg (off the smem crossbar), TROWS=128/NTH=128/grid=512,
// 4 CTAs/SM. R=4 x C=4 f32x2 register tile.

#define IN_DIM 784
#define DM     16
#define HID    6
#define NB     4
#define NC     10
#define KC     28            // floats per k-chunk (112B rows: conflict-free)
#define NCHUNK 28            // 784 / 28
#define NKQ    7             // float4 groups per chunk
#define TROWS  128           // rows per CTA tile
#define NTH    128

// smem float offsets
#define XBUF   (TROWS*KC)        // 3584 floats per buffer (14,336 B)
#define MBAR_F (2*XBUF)          // 7168 (byte 28672, 16B aligned)
#define SMEM_FLOATS (MBAR_F + 8)
#define HXS    0                 // hx tile aliases xbuf0 (128*17=2176 < 3584)

// reordered weights in global (written by pre-kernel)
__device__ __align__(16) float g_Wq[DM * IN_DIM];     // [kqg][jj][cg][k4]
__device__ __align__(16) float g_Dt[NB * DM * HID];   // [i][a][j]

__global__ void reorder_kernel(const float* __restrict__ We,
                               const float* __restrict__ Dw) {
    int idx = blockIdx.x * 256 + threadIdx.x;
    if (idx < DM * IN_DIM) {
        int j = idx / IN_DIM, k = idx - j * IN_DIM;
        // col j = jj*4 + cg ; offset = kqg*64 + jj*16 + cg*4 + k4
        g_Wq[(k >> 2) * (DM * 4) + (j >> 2) * 16 + (j & 3) * 4 + (k & 3)] = We[idx];
    }
    if (idx < NB * DM * HID) {
        int i = idx / (DM * HID), r = idx % (DM * HID);
        int j = r / HID, a = r % HID;
        g_Dt[i * (DM * HID) + a * DM + j] = Dw[idx];
    }
}

__device__ __forceinline__ void fma2(unsigned long long& acc,
                                     unsigned long long a, unsigned long long b) {
    asm("fma.rn.f32x2 %0, %1, %2, %0;" : "+l"(acc) : "l"(a), "l"(b));
}

#define MB_INIT(addr, cnt) \
    asm volatile("mbarrier.init.shared.b64 [%0], %1;" :: "r"(addr), "r"(cnt) : "memory")
#define MB_EXPECT_TX(addr, bytes) \
    asm volatile("mbarrier.arrive.expect_tx.shared.b64 _, [%0], %1;" :: "r"(addr), "r"(bytes) : "memory")
#define MB_WAIT(addr, parity) do {                                                  \
    asm volatile("{\n\t.reg .pred P;\n"                                             \
        "WLP%=:\n\tmbarrier.try_wait.parity.acquire.cta.shared::cta.b64 P, [%0], %1, 0x989680;\n" \
        "\t@P bra WDN%=;\n\tbra WLP%=;\nWDN%=:\n\t}"                                \
        :: "r"(addr), "r"(parity) : "memory"); } while (0)
#define TMA_2D(dst, tmapp, cx, cy, mb)                                              \
    asm volatile("cp.async.bulk.tensor.2d.shared::cta.global.tile.mbarrier::complete_tx::bytes " \
        "[%0], [%1, {%2, %3}], [%4];"                                               \
        :: "r"(dst), "l"(tmapp), "r"(cx), "r"(cy), "r"(mb) : "memory")

__global__ __launch_bounds__(NTH, 4)
void bilinear_resnet_kernel(const __grid_constant__ CUtensorMap tmap,
                            const float* __restrict__ Lw,
                            const float* __restrict__ Rw,
                            const float* __restrict__ Wh,
                            float* __restrict__ out,
                            int batch)
{
    extern __shared__ float sm[];
    const int tid = threadIdx.x;
    const unsigned smbase = (unsigned)__cvta_generic_to_shared(sm);
    const unsigned mb0 = smbase + MBAR_F * 4;
    const unsigned mb1 = mb0 + 8;
    const int row0 = blockIdx.x * TROWS;

    const int warp = tid >> 5, lane = tid & 31;
    const int rs = lane >> 2;          // 0..7 rowset
    const int cg = lane & 3;           // cols cg, cg+4, cg+8, cg+12
    const int rowbase = warp * 32 + rs;   // rows rowbase + 8i, i=0..3

    if (tid == 0) { MB_INIT(mb0, 1); MB_INIT(mb1, 1); }
    __syncthreads();

    if (tid == 0) {
        MB_EXPECT_TX(mb0, XBUF * 4);
        TMA_2D(smbase, &tmap, 0, row0, mb0);
        MB_EXPECT_TX(mb1, XBUF * 4);
        TMA_2D(smbase + XBUF * 4, &tmap, KC, row0, mb1);
    }

    unsigned long long acc[4][4];
    #pragma unroll
    for (int i = 0; i < 4; i++)
        #pragma unroll
        for (int jj = 0; jj < 4; jj++) acc[i][jj] = 0ull;

    const float* wgbase = g_Wq + cg * 4;

    for (int c = 0; c < NCHUNK; c++) {
        MB_WAIT((c & 1) ? mb1 : mb0, (c >> 1) & 1);

        const float* xb = sm + (c & 1) * XBUF;
        const float* wc = wgbase + c * (NKQ * DM * 4);
        #pragma unroll
        for (int kq = 0; kq < NKQ; kq++) {
            ulonglong2 wv[4];
            #pragma unroll
            for (int jj = 0; jj < 4; jj++)
                wv[jj] = __ldg((const ulonglong2*)(wc + kq * (DM * 4) + jj * 16));
            ulonglong2 xv[4];
            #pragma unroll
            for (int i = 0; i < 4; i++)
                xv[i] = *(const ulonglong2*)(xb + (rowbase + 8 * i) * KC + kq * 4);
            #pragma unroll
            for (int i = 0; i < 4; i++)
                #pragma unroll
                for (int jj = 0; jj < 4; jj++) {
                    fma2(acc[i][jj], xv[i].x, wv[jj].x);
                    fma2(acc[i][jj], xv[i].y, wv[jj].y);
                }
        }
        __syncthreads();   // everyone done reading buf (c&1)
        if (c + 2 < NCHUNK && tid == 0) {
            unsigned mb = (c & 1) ? mb1 : mb0;
            MB_EXPECT_TX(mb, XBUF * 4);
            TMA_2D(smbase + (c & 1) * XBUF * 4, &tmap, (c + 2) * KC, row0, mb);
        }
    }

    // ---- reduce f32x2 accs into hx tile (aliases xbuf0) ----
    #pragma unroll
    for (int i = 0; i < 4; i++) {
        int row = rowbase + 8 * i;
        #pragma unroll
        for (int jj = 0; jj < 4; jj++) {
            unsigned long long a = acc[i][jj];
            sm[HXS + row * 17 + jj * 4 + cg] =
                __uint_as_float((unsigned)a) + __uint_as_float((unsigned)(a >> 32));
        }
    }
    __syncthreads();

    // ---- phase 2: exactly one row per thread ----
    {
        float hx[DM];
        #pragma unroll
        for (int j = 0; j < DM; j++) hx[j] = sm[HXS + tid * 17 + j];

        const long long grow  = row0 + tid;
        const long long hbase = (long long)batch * NC;
        const long long hblk  = (long long)batch * HID;

        #pragma unroll
        for (int ib = 0; ib < NB; ib++) {
            float h[HID];
            #pragma unroll
            for (int a = 0; a < HID; a++) {
                const float4* lp = (const float4*)(Lw + ib * (HID * DM) + a * DM);
                const float4* rp = (const float4*)(Rw + ib * (HID * DM) + a * DM);
                float su = 0.f, sv = 0.f;
                #pragma unroll
                for (int q = 0; q < 4; q++) {
                    float4 l4 = __ldg(lp + q), r4 = __ldg(rp + q);
                    su = fmaf(l4.x, hx[q*4+0], fmaf(l4.y, hx[q*4+1],
                         fmaf(l4.z, hx[q*4+2], fmaf(l4.w, hx[q*4+3], su))));
                    sv = fmaf(r4.x, hx[q*4+0], fmaf(r4.y, hx[q*4+1],
                         fmaf(r4.z, hx[q*4+2], fmaf(r4.w, hx[q*4+3], sv))));
                }
                h[a] = su * sv;
            }
            {
                float* hp = out + hbase + (long long)ib * hblk + grow * HID;
                *(float2*)(hp + 0) = make_float2(h[0], h[1]);
                *(float2*)(hp + 2) = make_float2(h[2], h[3]);
                *(float2*)(hp + 4) = make_float2(h[4], h[5]);
            }
            #pragma unroll
            for (int a = 0; a < HID; a++) {
                const float4* dp = (const float4*)(g_Dt + ib * (DM * HID) + a * DM);
                #pragma unroll
                for (int q = 0; q < 4; q++) {
                    float4 d4 = dp[q];
                    hx[q*4+0] = fmaf(h[a], d4.x, hx[q*4+0]);
                    hx[q*4+1] = fmaf(h[a], d4.y, hx[q*4+1]);
                    hx[q*4+2] = fmaf(h[a], d4.z, hx[q*4+2]);
                    hx[q*4+3] = fmaf(h[a], d4.w, hx[q*4+3]);
                }
            }
        }

        float lg[NC];
        #pragma unroll
        for (int cc = 0; cc < NC; cc++) {
            const float4* wp = (const float4*)(Wh + cc * DM);
            float s = 0.f;
            #pragma unroll
            for (int q = 0; q < 4; q++) {
                float4 w4 = __ldg(wp + q);
                s = fmaf(w4.x, hx[q*4+0], fmaf(w4.y, hx[q*4+1],
                    fmaf(w4.z, hx[q*4+2], fmaf(w4.w, hx[q*4+3], s))));
            }
            lg[cc] = s;
        }
        float* op = out + grow * NC;
        *(float2*)(op + 0) = make_float2(lg[0], lg[1]);
        *(float2*)(op + 2) = make_float2(lg[2], lg[3]);
        *(float2*)(op + 4) = make_float2(lg[4], lg[5]);
        *(float2*)(op + 6) = make_float2(lg[6], lg[7]);
        *(float2*)(op + 8) = make_float2(lg[8], lg[9]);
    }
}

typedef CUresult (*PFN_encodeTiled)(
    CUtensorMap*, CUtensorMapDataType, cuuint32_t, void*,
    const cuuint64_t*, const cuuint64_t*, const cuuint32_t*, const cuuint32_t*,
    CUtensorMapInterleave, CUtensorMapSwizzle, CUtensorMapL2promotion,
    CUtensorMapFloatOOBfill);

extern "C" void kernel_launch(void* const* d_in, const int* in_sizes, int n_in,
                              void* d_out, int out_size)
{
    const float* x  = (const float*)d_in[0];
    const float* We = (const float*)d_in[1];
    const float* Lw = (const float*)d_in[2];
    const float* Rw = (const float*)d_in[3];
    const float* Dw = (const float*)d_in[4];
    const float* Wh = (const float*)d_in[5];
    float* out = (float*)d_out;

    int batch = in_sizes[0] / IN_DIM;   // 65536
    int grid  = batch / TROWS;          // 512

    CUtensorMap tmap;
    {
        void* fp = nullptr;
        cudaDriverEntryPointQueryResult st;
        cudaGetDriverEntryPoint("cuTensorMapEncodeTiled", &fp,
                                cudaEnableDefault, &st);
        PFN_encodeTiled enc = (PFN_encodeTiled)fp;
        cuuint64_t dims[2]    = {IN_DIM, (cuuint64_t)batch};
        cuuint64_t strides[1] = {IN_DIM * sizeof(float)};
        cuuint32_t box[2]     = {KC, TROWS};
        cuuint32_t estr[2]    = {1, 1};
        enc(&tmap, CU_TENSOR_MAP_DATA_TYPE_FLOAT32, 2, (void*)x,
            dims, strides, box, estr,
            CU_TENSOR_MAP_INTERLEAVE_NONE, CU_TENSOR_MAP_SWIZZLE_NONE,
            CU_TENSOR_MAP_L2_PROMOTION_L2_128B, CU_TENSOR_MAP_FLOAT_OOB_FILL_NONE);
    }

    reorder_kernel<<<(DM * IN_DIM + 255) / 256, 256>>>(We, Dw);

    size_t smem = (size_t)SMEM_FLOATS * sizeof(float);   // ~28.7 KB
    cudaFuncSetAttribute(bilinear_resnet_kernel,
                         cudaFuncAttributeMaxDynamicSharedMemorySize, (int)smem);
    bilinear_resnet_kernel<<<grid, NTH, smem>>>(tmap, Lw, Rw, Wh, out, batch);
}